// round 1
// baseline (speedup 1.0000x reference)
#include <cuda_runtime.h>

// GCN with learnable edge gates, but output = log_softmax(h3[index]) only.
// Strategy: prune to the 3-hop in-neighborhood dependence cone of `index`.
// Full-edge scans are needed only for (a) degree accumulation, (b) frontier
// discovery. Dense math runs on ~5000 nodes instead of 50000.

#define NN 50000
#define NE 800000
#define DH 64
#define DIN 128
#define NC 10

// ---------------- device scratch (no allocation allowed) ----------------
__device__ float g_deg[NN];                  // deg, then dinv in-place
__device__ unsigned char g_m1[NN], g_m2[NN], g_m3[NN];
__device__ int g_el1[NE], g_el2[NE], g_el3[NE];
__device__ int g_n1, g_n2, g_n3, g_c1, g_c2, g_c3;
__device__ int g_l1[NN], g_l2[NN], g_l3[NN];
__device__ float g_y1[(size_t)NN * DH];      // x@W1 rows (frontier3)
__device__ float g_h1[(size_t)NN * DH];      // layer1 agg (frontier2)
__device__ float g_y2[(size_t)NN * DH];      // relu(h1+b1)@W2 (frontier2)
__device__ float g_h2[(size_t)NN * DH];      // layer2 agg (frontier1)
__device__ float g_y3[(size_t)NN * NC];      // relu(h2+b2)@W3 (frontier1)
__device__ int g_is64;                        // edge_index dtype flag

__device__ __forceinline__ float sigf(float v) { return 1.f / (1.f + expf(-v)); }

// edge_index is (2,E) row-major; element i in flattened [src... dst...] order.
__device__ __forceinline__ int eidx(const void* ei, long long i) {
    if (g_is64) return (int)((const long long*)ei)[i];
    return ((const int*)ei)[i];
}

// ---------------- kernels ----------------

__global__ void k_init(const void* ei, const int* idxp) {
    int v = blockIdx.x * blockDim.x + threadIdx.x;
    if (v == 0) {
        g_n1 = 0; g_n2 = 0; g_n3 = 0;
        g_c1 = 0; g_c2 = 0; g_c3 = 0;
        // dtype sniff: int64 edge values < 50000 => high words all zero.
        const int* w = (const int*)ei;
        int any = 0;
        #pragma unroll
        for (int k = 0; k < 32; k++) any |= w[2 * k + 1];
        g_is64 = (any == 0) ? 1 : 0;
    }
    if (v < NN) {
        g_deg[v] = 1.0f;            // self-loop weight
        g_m1[v] = 0; g_m2[v] = 0; g_m3[v] = 0;
        if (v == *idxp) g_m1[v] = 1;
    }
}

// Full scan: degree accumulation + frontier1 (edges into `index`).
__global__ void k_scan1(const void* ei, const float* wp, const int* idxp, int E) {
    int e = blockIdx.x * blockDim.x + threadIdx.x;
    if (e >= E) return;
    int d = eidx(ei, (long long)E + e);
    atomicAdd(&g_deg[d], sigf(wp[e]));
    if (d == *idxp) {
        int s = eidx(ei, e);
        g_m1[s] = 1;
        int p = atomicAdd(&g_n1, 1);
        g_el1[p] = e;
    }
}

__global__ void k_dinv() {
    int v = blockIdx.x * blockDim.x + threadIdx.x;
    if (v < NN) g_deg[v] = rsqrtf(g_deg[v]);
}

// Frontier2 = frontier1 ∪ in-neighbors(frontier1); collect edges into frontier1.
__global__ void k_scan2(const void* ei, int E) {
    int t = blockIdx.x * blockDim.x + threadIdx.x;
    if (t < NN) {
        if (g_m1[t]) g_m2[t] = 1;   // only ever writes 1 -> race-free
        return;
    }
    int e = t - NN;
    if (e >= E) return;
    int d = eidx(ei, (long long)E + e);
    if (g_m1[d]) {
        int s = eidx(ei, e);
        g_m2[s] = 1;
        int p = atomicAdd(&g_n2, 1);
        g_el2[p] = e;
    }
}

// Frontier3 = frontier2 ∪ in-neighbors(frontier2); collect edges into frontier2.
__global__ void k_scan3(const void* ei, int E) {
    int t = blockIdx.x * blockDim.x + threadIdx.x;
    if (t < NN) {
        if (g_m2[t]) g_m3[t] = 1;
        return;
    }
    int e = t - NN;
    if (e >= E) return;
    int d = eidx(ei, (long long)E + e);
    if (g_m2[d]) {
        int s = eidx(ei, e);
        g_m3[s] = 1;
        int p = atomicAdd(&g_n3, 1);
        g_el3[p] = e;
    }
}

// Compact masks into node lists; zero the accumulator rows we'll scatter into.
__global__ void k_compact() {
    int v = blockIdx.x * blockDim.x + threadIdx.x;
    if (v >= NN) return;
    if (g_m1[v]) {
        int p = atomicAdd(&g_c1, 1);
        g_l1[p] = v;
        float* r = &g_h2[(size_t)v * DH];
        #pragma unroll
        for (int j = 0; j < DH; j++) r[j] = 0.f;
    }
    if (g_m2[v]) {
        int p = atomicAdd(&g_c2, 1);
        g_l2[p] = v;
        float* r = &g_h1[(size_t)v * DH];
        #pragma unroll
        for (int j = 0; j < DH; j++) r[j] = 0.f;
    }
    if (g_m3[v]) {
        int p = atomicAdd(&g_c3, 1);
        g_l3[p] = v;
    }
}

// y1[v] = x[v] @ W1 for v in frontier3. One warp per node; W1 in smem.
__global__ void k_xw1(const float* x, const float* W1) {
    __shared__ float sW[DIN * DH];       // 32 KB
    __shared__ float sx[8][DIN];         // per-warp row buffer
    for (int i = threadIdx.x; i < DIN * DH; i += blockDim.x) sW[i] = W1[i];
    __syncthreads();
    int warp = threadIdx.x >> 5, lane = threadIdx.x & 31;
    int gw = blockIdx.x * (blockDim.x >> 5) + warp;
    int nw = gridDim.x * (blockDim.x >> 5);
    int c3 = g_c3;
    for (int i = gw; i < c3; i += nw) {
        int v = g_l3[i];
        const float* xr = x + (size_t)v * DIN;
        for (int k = lane; k < DIN; k += 32) sx[warp][k] = xr[k];
        __syncwarp();
        float a0 = 0.f, a1 = 0.f;
        #pragma unroll 16
        for (int k = 0; k < DIN; k++) {
            float xv = sx[warp][k];
            a0 = fmaf(xv, sW[k * DH + lane], a0);
            a1 = fmaf(xv, sW[k * DH + lane + 32], a1);
        }
        float* yr = &g_y1[(size_t)v * DH];
        yr[lane] = a0; yr[lane + 32] = a1;
        __syncwarp();
    }
}

// h1[dst] += norm * y1[src] over EL3 edges, plus self-loops for frontier2.
__global__ void k_scatter1(const void* ei, const float* wp, int E) {
    int lane = threadIdx.x & 31;
    int gw = (blockIdx.x * blockDim.x + threadIdx.x) >> 5;
    int nw = (gridDim.x * blockDim.x) >> 5;
    int n3 = g_n3, c2 = g_c2;
    int tot = n3 + c2;
    for (int i = gw; i < tot; i += nw) {
        int s, d; float norm;
        if (i < n3) {
            int e = g_el3[i];
            s = eidx(ei, e); d = eidx(ei, (long long)E + e);
            norm = g_deg[s] * sigf(wp[e]) * g_deg[d];
        } else {
            s = d = g_l2[i - n3];
            float dv = g_deg[s];
            norm = dv * dv;
        }
        const float* ys = &g_y1[(size_t)s * DH];
        float* hd = &g_h1[(size_t)d * DH];
        atomicAdd(&hd[lane],      norm * ys[lane]);
        atomicAdd(&hd[lane + 32], norm * ys[lane + 32]);
    }
}

// y2[v] = relu(h1[v] + b1) @ W2 for v in frontier2.
__global__ void k_xw2(const float* W2, const float* b1) {
    __shared__ float sW[DH * DH];        // 16 KB
    __shared__ float sb[DH];
    __shared__ float sx[8][DH];
    for (int i = threadIdx.x; i < DH * DH; i += blockDim.x) sW[i] = W2[i];
    if (threadIdx.x < DH) sb[threadIdx.x] = b1[threadIdx.x];
    __syncthreads();
    int warp = threadIdx.x >> 5, lane = threadIdx.x & 31;
    int gw = blockIdx.x * (blockDim.x >> 5) + warp;
    int nw = gridDim.x * (blockDim.x >> 5);
    int c2 = g_c2;
    for (int i = gw; i < c2; i += nw) {
        int v = g_l2[i];
        const float* hr = &g_h1[(size_t)v * DH];
        sx[warp][lane]      = fmaxf(hr[lane]      + sb[lane],      0.f);
        sx[warp][lane + 32] = fmaxf(hr[lane + 32] + sb[lane + 32], 0.f);
        __syncwarp();
        float a0 = 0.f, a1 = 0.f;
        #pragma unroll 16
        for (int k = 0; k < DH; k++) {
            float xv = sx[warp][k];
            a0 = fmaf(xv, sW[k * DH + lane], a0);
            a1 = fmaf(xv, sW[k * DH + lane + 32], a1);
        }
        float* yr = &g_y2[(size_t)v * DH];
        yr[lane] = a0; yr[lane + 32] = a1;
        __syncwarp();
    }
}

// h2[dst] += norm * y2[src] over EL2 edges, plus self-loops for frontier1.
__global__ void k_scatter2(const void* ei, const float* wp, int E) {
    int lane = threadIdx.x & 31;
    int gw = (blockIdx.x * blockDim.x + threadIdx.x) >> 5;
    int nw = (gridDim.x * blockDim.x) >> 5;
    int n2 = g_n2, c1 = g_c1;
    int tot = n2 + c1;
    for (int i = gw; i < tot; i += nw) {
        int s, d; float norm;
        if (i < n2) {
            int e = g_el2[i];
            s = eidx(ei, e); d = eidx(ei, (long long)E + e);
            norm = g_deg[s] * sigf(wp[e]) * g_deg[d];
        } else {
            s = d = g_l1[i - n2];
            float dv = g_deg[s];
            norm = dv * dv;
        }
        const float* ys = &g_y2[(size_t)s * DH];
        float* hd = &g_h2[(size_t)d * DH];
        atomicAdd(&hd[lane],      norm * ys[lane]);
        atomicAdd(&hd[lane + 32], norm * ys[lane + 32]);
    }
}

// y3[v] = relu(h2[v] + b2) @ W3 for v in frontier1 (~17 nodes).
__global__ void k_y3(const float* W3, const float* b2) {
    int lane = threadIdx.x & 31;
    int gw = (blockIdx.x * blockDim.x + threadIdx.x) >> 5;
    int nw = (gridDim.x * blockDim.x) >> 5;
    int c1 = g_c1;
    for (int i = gw; i < c1; i += nw) {
        int v = g_l1[i];
        if (lane < NC) {
            float acc = 0.f;
            const float* hr = &g_h2[(size_t)v * DH];
            #pragma unroll
            for (int k = 0; k < DH; k++) {
                float hv = fmaxf(hr[k] + b2[k], 0.f);
                acc = fmaf(hv, W3[k * NC + lane], acc);
            }
            g_y3[(size_t)v * NC + lane] = acc;
        }
    }
}

// Final: out = log_softmax( b3 + sum over edges into index of norm*y3[src]
//                               + dinv[idx]^2 * y3[idx] )
__global__ void k_final(const void* ei, const float* wp, const int* idxp,
                        const float* b3, float* out, int E) {
    __shared__ float sv[NC];
    int j = threadIdx.x;
    int idx = *idxp;
    float di = g_deg[idx];
    if (j < NC) {
        float acc = b3[j] + di * di * g_y3[(size_t)idx * NC + j];
        int n1 = g_n1;
        for (int i = 0; i < n1; i++) {
            int e = g_el1[i];
            int s = eidx(ei, e);
            float norm = g_deg[s] * sigf(wp[e]) * di;
            acc = fmaf(norm, g_y3[(size_t)s * NC + j], acc);
        }
        sv[j] = acc;
    }
    __syncthreads();
    if (j == 0) {
        float m = sv[0];
        #pragma unroll
        for (int t = 1; t < NC; t++) m = fmaxf(m, sv[t]);
        float ssum = 0.f;
        #pragma unroll
        for (int t = 0; t < NC; t++) ssum += expf(sv[t] - m);
        float l = m + logf(ssum);
        #pragma unroll
        for (int t = 0; t < NC; t++) out[t] = sv[t] - l;
    }
}

// ---------------- launch ----------------
extern "C" void kernel_launch(void* const* d_in, const int* in_sizes, int n_in,
                              void* d_out, int out_size) {
    const float* x   = (const float*)d_in[0];
    const void*  ei  = d_in[1];                 // (2,E) src row then dst row
    const float* wp  = (const float*)d_in[2];
    const float* W1  = (const float*)d_in[3];
    const float* b1  = (const float*)d_in[4];
    const float* W2  = (const float*)d_in[5];
    const float* b2  = (const float*)d_in[6];
    const float* W3  = (const float*)d_in[7];
    const float* b3  = (const float*)d_in[8];
    const int*  idxp = (const int*)d_in[9];     // low word valid for i32/i64
    float* out = (float*)d_out;

    int E = in_sizes[2];                        // edge count from weights
    if (E > NE) E = NE;

    k_init<<<(NN + 255) / 256, 256>>>(ei, idxp);
    k_scan1<<<(E + 255) / 256, 256>>>(ei, wp, idxp, E);
    k_dinv<<<(NN + 255) / 256, 256>>>();
    k_scan2<<<(NN + E + 255) / 256, 256>>>(ei, E);
    k_scan3<<<(NN + E + 255) / 256, 256>>>(ei, E);
    k_compact<<<(NN + 255) / 256, 256>>>();
    k_xw1<<<120, 256>>>(x, W1);
    k_scatter1<<<64, 256>>>(ei, wp, E);
    k_xw2<<<32, 256>>>(W2, b1);
    k_scatter2<<<16, 256>>>(ei, wp, E);
    k_y3<<<4, 64>>>(W3, b2);
    k_final<<<1, 32>>>(ei, wp, idxp, b3, out, E);
}